// round 1
// baseline (speedup 1.0000x reference)
#include <cuda_runtime.h>

// VectorP1FunctionSpace: evaluate two P1 FEM interpolants (weights wx, wy) of a
// structured 32x32 triangulation of [0,1]^2 at query points x.
//
// The reference's relu/min hat-function construction reduces exactly to
// barycentric interpolation on the containing triangle (see analysis):
//   cell (i,j) = floor(32*x); lower-right tri (v00,v10,v11) when fx>=fy with
//   barycentrics (1-fx, fx-fy, fy); upper-left tri (v00,v11,v01) otherwise
//   with (1-fy, fx, fy-fx).  Vertex index v(i,j) = i*33 + j.

#define NXY    32
#define NYP1   33

__global__ void vp1_eval_kernel(const float2* __restrict__ x,
                                const float*  __restrict__ wx,
                                const float*  __restrict__ wy,
                                float2*       __restrict__ out,
                                int total)
{
    int idx = blockIdx.x * blockDim.x + threadIdx.x;
    if (idx >= total) return;

    float2 p = x[idx];
    float sx = p.x * (float)NXY;
    float sy = p.y * (float)NXY;

    int i = (int)floorf(sx);
    int j = (int)floorf(sy);
    i = min(max(i, 0), NXY - 1);
    j = min(max(j, 0), NXY - 1);

    float fx = sx - (float)i;
    float fy = sy - (float)j;

    int v00 = i * NYP1 + j;       // (i,   j)
    int v10 = v00 + NYP1;         // (i+1, j)
    int v01 = v00 + 1;            // (i,   j+1)
    int v11 = v10 + 1;            // (i+1, j+1)

    int   va, vb, vc;
    float l0, l1, l2;
    if (fx >= fy) {               // lower-right triangle (v00, v10, v11)
        va = v00; vb = v10; vc = v11;
        l0 = 1.0f - fx; l1 = fx - fy; l2 = fy;
    } else {                      // upper-left triangle (v00, v11, v01)
        va = v00; vb = v11; vc = v01;
        l0 = 1.0f - fy; l1 = fx; l2 = fy - fx;
    }

    float ox = l0 * __ldg(&wx[va]) + l1 * __ldg(&wx[vb]) + l2 * __ldg(&wx[vc]);
    float oy = l0 * __ldg(&wy[va]) + l1 * __ldg(&wy[vb]) + l2 * __ldg(&wy[vc]);

    out[idx] = make_float2(ox, oy);
}

extern "C" void kernel_launch(void* const* d_in, const int* in_sizes, int n_in,
                              void* d_out, int out_size)
{
    const float* x  = (const float*)d_in[0];   // [B, N, 2]
    // d_in[1] = W [V,6,2], d_in[2] = c [V,6]  -- not needed (analytic form)
    const float* wx = (const float*)d_in[3];   // [V]
    const float* wy = (const float*)d_in[4];   // [V]
    float* out = (float*)d_out;                // [B, N, 2]

    int total = out_size / 2;                  // number of query points (B*N)

    int threads = 256;
    int blocks  = (total + threads - 1) / threads;
    vp1_eval_kernel<<<blocks, threads>>>((const float2*)x, wx, wy,
                                         (float2*)out, total);
}